// round 4
// baseline (speedup 1.0000x reference)
#include <cuda_runtime.h>
#include <mma.h>

using namespace nvcuda;

#define HDIM 2048
#define NEXP 16
#define TOPK 4
#define IDIM 1408
#define ISDIM 2816
#define NTOK 1024

// ---------------- scratch (device globals; no allocation) ----------------
__device__ float g_act[(size_t)NEXP * NTOK * IDIM];     // routed SwiGLU activations, [e][slot][I]
__device__ float g_shact[(size_t)NTOK * ISDIM];         // shared-expert activations
__device__ int   g_list[NEXP * NTOK];                   // token ids per expert (compacted)
__device__ float g_lwt[NEXP * NTOK];                    // combine weight per (expert, slot)
__device__ int   g_cnt[NEXP];                           // tokens per expert
__device__ int   g_tki[NTOK * TOPK];                    // top-k expert idx per token
__device__ float g_tkw[NTOK * TOPK];                    // renormalized top-k weight

// ---------------- router: warp per token ----------------
__global__ void router_kernel(const float* __restrict__ x, const float* __restrict__ gw) {
    int warp = threadIdx.x >> 5;
    int lane = threadIdx.x & 31;
    int t = blockIdx.x * 4 + warp;
    if (t >= NTOK) return;

    float acc[NEXP];
#pragma unroll
    for (int e = 0; e < NEXP; e++) acc[e] = 0.f;

    for (int h = lane * 4; h < HDIM; h += 32 * 4) {
        float4 xv = *(const float4*)&x[(size_t)t * HDIM + h];
#pragma unroll
        for (int e = 0; e < NEXP; e++) {
            float4 gv = *(const float4*)&gw[(size_t)e * HDIM + h];
            acc[e] = fmaf(xv.x, gv.x, acc[e]);
            acc[e] = fmaf(xv.y, gv.y, acc[e]);
            acc[e] = fmaf(xv.z, gv.z, acc[e]);
            acc[e] = fmaf(xv.w, gv.w, acc[e]);
        }
    }
#pragma unroll
    for (int e = 0; e < NEXP; e++) {
#pragma unroll
        for (int off = 16; off; off >>= 1)
            acc[e] += __shfl_xor_sync(0xffffffffu, acc[e], off);
    }

    if (lane == 0) {
        float mx = acc[0];
#pragma unroll
        for (int e = 1; e < NEXP; e++) mx = fmaxf(mx, acc[e]);
        float ex[NEXP];
#pragma unroll
        for (int e = 0; e < NEXP; e++) ex[e] = __expf(acc[e] - mx);
        // top-4 by ex (monotone with softmax score); softmax denom cancels in renorm.
        bool used[NEXP];
#pragma unroll
        for (int e = 0; e < NEXP; e++) used[e] = false;
        int idx[TOPK]; float tw[TOPK]; float ws = 0.f;
#pragma unroll
        for (int k = 0; k < TOPK; k++) {
            int bi = -1; float bv = -1.f;
#pragma unroll
            for (int e = 0; e < NEXP; e++)
                if (!used[e] && ex[e] > bv) { bv = ex[e]; bi = e; }
            used[bi] = true; idx[k] = bi; tw[k] = bv; ws += bv;
        }
        float inv = 1.f / ws;
#pragma unroll
        for (int k = 0; k < TOPK; k++) {
            g_tki[t * TOPK + k] = idx[k];
            g_tkw[t * TOPK + k] = tw[k] * inv;
        }
    }
}

// ---------------- deterministic per-expert compaction ----------------
__global__ void build_lists_kernel() {
    int e = blockIdx.x;
    int t = threadIdx.x;   // 1024 threads == NTOK
    bool sel = false; float w = 0.f;
#pragma unroll
    for (int k = 0; k < TOPK; k++) {
        if (g_tki[t * TOPK + k] == e) { sel = true; w = g_tkw[t * TOPK + k]; }
    }
    unsigned m = __ballot_sync(0xffffffffu, sel);
    int lane = t & 31, wid = t >> 5;
    __shared__ int wcnt[32], woff[32];
    if (lane == 0) wcnt[wid] = __popc(m);
    __syncthreads();
    if (t < 32) {
        int v = wcnt[t];
        int s = v;
#pragma unroll
        for (int off = 1; off < 32; off <<= 1) {
            int o = __shfl_up_sync(0xffffffffu, s, off);
            if (t >= off) s += o;
        }
        woff[t] = s - v;
        if (t == 31) g_cnt[e] = s;   // written every launch -> no memset needed
    }
    __syncthreads();
    if (sel) {
        int pos = woff[wid] + __popc(m & ((1u << lane) - 1));
        g_list[e * NTOK + pos] = t;
        g_lwt[e * NTOK + pos] = w;
    }
}

// ---------------- GEMM1: fused gate+up (+SwiGLU) ----------------
// BM=BN=64, BK=16, 128 threads (4 warps, 2x2), wmma tf32 m16n16k8.
// Scratch outputs are device globals referenced directly from device code.
template <bool ROUTED>
__global__ __launch_bounds__(128)
void gemm_gateup(const float* __restrict__ X,
                 const float* __restrict__ Wg,
                 const float* __restrict__ Wu,
                 int ldb) {
    const int tid = threadIdx.x;
    const int wid = tid >> 5;
    const int wm = wid >> 1, wn = wid & 1;

    const int n0 = blockIdx.x * 64;
    const int m0 = blockIdx.y * 64;

    int e = 0, cnt = NTOK;
    const float* bg = Wg;
    const float* bu = Wu;
    if (ROUTED) {
        e = blockIdx.z;
        cnt = g_cnt[e];
        if (m0 >= cnt) return;
        bg = Wg + (size_t)e * HDIM * IDIM;
        bu = Wu + (size_t)e * HDIM * IDIM;
    }

    __shared__ float As[64 * 16];
    __shared__ float Bgs[16 * 64];
    __shared__ float Bus[16 * 64];
    __shared__ float Cg[64 * 64];
    __shared__ float Cu[64 * 64];
    __shared__ int   rowtok[64];
    __shared__ float roww[64];

    if (tid < 64) {
        int slot = m0 + tid;
        if (ROUTED) {
            rowtok[tid] = (slot < cnt) ? g_list[e * NTOK + slot] : 0;
            roww[tid]   = (slot < cnt) ? g_lwt[e * NTOK + slot] : 0.f;
        } else {
            rowtok[tid] = slot;
        }
    }
    __syncthreads();

    wmma::fragment<wmma::accumulator, 16, 16, 8, float> accg[2][2], accu[2][2];
#pragma unroll
    for (int i = 0; i < 2; i++)
#pragma unroll
        for (int j = 0; j < 2; j++) {
            wmma::fill_fragment(accg[i][j], 0.f);
            wmma::fill_fragment(accu[i][j], 0.f);
        }

    for (int k0 = 0; k0 < HDIM; k0 += 16) {
        // A tile: 64 rows x 16 cols = 256 float4
        {
            int i4 = tid * 2;               // 2 float4 per thread
#pragma unroll
            for (int q = 0; q < 2; q++, i4++) {
                int r = i4 >> 2, c4 = (i4 & 3) * 4;
                *(float4*)&As[r * 16 + c4] =
                    *(const float4*)&X[(size_t)rowtok[r] * HDIM + k0 + c4];
            }
        }
        // B tiles: 16 rows x 64 cols = 256 float4 each
        {
            int i4 = tid * 2;
#pragma unroll
            for (int q = 0; q < 2; q++, i4++) {
                int r = i4 >> 4, c4 = (i4 & 15) * 4;
                size_t g = (size_t)(k0 + r) * ldb + n0 + c4;
                *(float4*)&Bgs[r * 64 + c4] = *(const float4*)&bg[g];
                *(float4*)&Bus[r * 64 + c4] = *(const float4*)&bu[g];
            }
        }
        __syncthreads();

#pragma unroll
        for (int kk = 0; kk < 16; kk += 8) {
            wmma::fragment<wmma::matrix_a, 16, 16, 8, wmma::precision::tf32, wmma::row_major> fa[2];
            wmma::fragment<wmma::matrix_b, 16, 16, 8, wmma::precision::tf32, wmma::row_major> fbg[2], fbu[2];
#pragma unroll
            for (int i = 0; i < 2; i++) {
                wmma::load_matrix_sync(fa[i], &As[(wm * 32 + i * 16) * 16 + kk], 16);
#pragma unroll
                for (int tt = 0; tt < fa[i].num_elements; tt++)
                    fa[i].x[tt] = wmma::__float_to_tf32(fa[i].x[tt]);
            }
#pragma unroll
            for (int j = 0; j < 2; j++) {
                wmma::load_matrix_sync(fbg[j], &Bgs[kk * 64 + wn * 32 + j * 16], 64);
                wmma::load_matrix_sync(fbu[j], &Bus[kk * 64 + wn * 32 + j * 16], 64);
#pragma unroll
                for (int tt = 0; tt < fbg[j].num_elements; tt++) {
                    fbg[j].x[tt] = wmma::__float_to_tf32(fbg[j].x[tt]);
                    fbu[j].x[tt] = wmma::__float_to_tf32(fbu[j].x[tt]);
                }
            }
#pragma unroll
            for (int i = 0; i < 2; i++)
#pragma unroll
                for (int j = 0; j < 2; j++) {
                    wmma::mma_sync(accg[i][j], fa[i], fbg[j], accg[i][j]);
                    wmma::mma_sync(accu[i][j], fa[i], fbu[j], accu[i][j]);
                }
        }
        __syncthreads();
    }

#pragma unroll
    for (int i = 0; i < 2; i++)
#pragma unroll
        for (int j = 0; j < 2; j++) {
            wmma::store_matrix_sync(&Cg[(wm * 32 + i * 16) * 64 + wn * 32 + j * 16], accg[i][j], 64, wmma::mem_row_major);
            wmma::store_matrix_sync(&Cu[(wm * 32 + i * 16) * 64 + wn * 32 + j * 16], accu[i][j], 64, wmma::mem_row_major);
        }
    __syncthreads();

    // epilogue: silu(g)*u (*weight), vectorized stores to device-global scratch
    for (int idx = tid * 4; idx < 64 * 64; idx += 128 * 4) {
        int r = idx >> 6, c = idx & 63;
        float4 gv = *(float4*)&Cg[idx];
        float4 uv = *(float4*)&Cu[idx];
        float4 a;
        a.x = gv.x / (1.f + __expf(-gv.x)) * uv.x;
        a.y = gv.y / (1.f + __expf(-gv.y)) * uv.y;
        a.z = gv.z / (1.f + __expf(-gv.z)) * uv.z;
        a.w = gv.w / (1.f + __expf(-gv.w)) * uv.w;
        if (ROUTED) {
            float w = roww[r];
            a.x *= w; a.y *= w; a.z *= w; a.w *= w;
            *(float4*)&g_act[((size_t)(e * NTOK + m0 + r)) * IDIM + n0 + c] = a;
        } else {
            *(float4*)&g_shact[(size_t)(m0 + r) * ISDIM + n0 + c] = a;
        }
    }
}

// ---------------- GEMM2: down projection ----------------
template <bool ROUTED>
__global__ __launch_bounds__(128)
void gemm_down(const float* __restrict__ W, int KK, float* __restrict__ Y) {
    const int tid = threadIdx.x;
    const int wid = tid >> 5;
    const int wm = wid >> 1, wn = wid & 1;

    const int n0 = blockIdx.x * 64;
    const int m0 = blockIdx.y * 64;

    int e = 0, cnt = NTOK;
    const float* bw = W;
    const float* Abase;
    int lda;
    if (ROUTED) {
        e = blockIdx.z;
        cnt = g_cnt[e];
        if (m0 >= cnt) return;
        bw = W + (size_t)e * IDIM * HDIM;
        Abase = g_act + (size_t)e * NTOK * IDIM;
        lda = IDIM;
    } else {
        Abase = g_shact;
        lda = ISDIM;
    }

    __shared__ float As[64 * 16];
    __shared__ float Bs[16 * 64];
    __shared__ float Cs[64 * 64];
    __shared__ int   rowtok[64];

    if (ROUTED && tid < 64) {
        int slot = m0 + tid;
        rowtok[tid] = (slot < cnt) ? g_list[e * NTOK + slot] : -1;
    }
    __syncthreads();

    wmma::fragment<wmma::accumulator, 16, 16, 8, float> acc[2][2];
#pragma unroll
    for (int i = 0; i < 2; i++)
#pragma unroll
        for (int j = 0; j < 2; j++) wmma::fill_fragment(acc[i][j], 0.f);

    for (int k0 = 0; k0 < KK; k0 += 16) {
        {
            int i4 = tid * 2;
#pragma unroll
            for (int q = 0; q < 2; q++, i4++) {
                int r = i4 >> 2, c4 = (i4 & 3) * 4;
                *(float4*)&As[r * 16 + c4] =
                    *(const float4*)&Abase[(size_t)(m0 + r) * lda + k0 + c4];
            }
        }
        {
            int i4 = tid * 2;
#pragma unroll
            for (int q = 0; q < 2; q++, i4++) {
                int r = i4 >> 4, c4 = (i4 & 15) * 4;
                *(float4*)&Bs[r * 64 + c4] =
                    *(const float4*)&bw[(size_t)(k0 + r) * HDIM + n0 + c4];
            }
        }
        __syncthreads();

#pragma unroll
        for (int kk = 0; kk < 16; kk += 8) {
            wmma::fragment<wmma::matrix_a, 16, 16, 8, wmma::precision::tf32, wmma::row_major> fa[2];
            wmma::fragment<wmma::matrix_b, 16, 16, 8, wmma::precision::tf32, wmma::row_major> fb[2];
#pragma unroll
            for (int i = 0; i < 2; i++) {
                wmma::load_matrix_sync(fa[i], &As[(wm * 32 + i * 16) * 16 + kk], 16);
#pragma unroll
                for (int tt = 0; tt < fa[i].num_elements; tt++)
                    fa[i].x[tt] = wmma::__float_to_tf32(fa[i].x[tt]);
            }
#pragma unroll
            for (int j = 0; j < 2; j++) {
                wmma::load_matrix_sync(fb[j], &Bs[kk * 64 + wn * 32 + j * 16], 64);
#pragma unroll
                for (int tt = 0; tt < fb[j].num_elements; tt++)
                    fb[j].x[tt] = wmma::__float_to_tf32(fb[j].x[tt]);
            }
#pragma unroll
            for (int i = 0; i < 2; i++)
#pragma unroll
                for (int j = 0; j < 2; j++)
                    wmma::mma_sync(acc[i][j], fa[i], fb[j], acc[i][j]);
        }
        __syncthreads();
    }

#pragma unroll
    for (int i = 0; i < 2; i++)
#pragma unroll
        for (int j = 0; j < 2; j++)
            wmma::store_matrix_sync(&Cs[(wm * 32 + i * 16) * 64 + wn * 32 + j * 16], acc[i][j], 64, wmma::mem_row_major);
    __syncthreads();

    for (int idx = tid * 4; idx < 64 * 64; idx += 128 * 4) {
        int r = idx >> 6, c = idx & 63;
        if (ROUTED) {
            int t = rowtok[r];
            if (t >= 0) {
                atomicAdd(&Y[(size_t)t * HDIM + n0 + c + 0], Cs[idx + 0]);
                atomicAdd(&Y[(size_t)t * HDIM + n0 + c + 1], Cs[idx + 1]);
                atomicAdd(&Y[(size_t)t * HDIM + n0 + c + 2], Cs[idx + 2]);
                atomicAdd(&Y[(size_t)t * HDIM + n0 + c + 3], Cs[idx + 3]);
            }
        } else {
            *(float4*)&Y[(size_t)(m0 + r) * HDIM + n0 + c] = *(float4*)&Cs[idx];
        }
    }
}

// ---------------- launch ----------------
extern "C" void kernel_launch(void* const* d_in, const int* in_sizes, int n_in,
                              void* d_out, int out_size) {
    const float* x       = (const float*)d_in[0];   // [1,1024,2048]
    const float* gate_w  = (const float*)d_in[1];   // [16,2048]
    const float* w_gate  = (const float*)d_in[2];   // [16,2048,1408]
    const float* w_up    = (const float*)d_in[3];
    const float* w_down  = (const float*)d_in[4];   // [16,1408,2048]
    const float* sw_gate = (const float*)d_in[5];   // [2048,2816]
    const float* sw_up   = (const float*)d_in[6];
    const float* sw_down = (const float*)d_in[7];   // [2816,2048]
    float* y = (float*)d_out;

    router_kernel<<<NTOK / 4, 128>>>(x, gate_w);
    build_lists_kernel<<<NEXP, NTOK>>>();

    // shared expert (writes y fully) before routed scatter-adds
    gemm_gateup<false><<<dim3(ISDIM / 64, NTOK / 64), 128>>>(x, sw_gate, sw_up, ISDIM);
    gemm_down<false><<<dim3(HDIM / 64, NTOK / 64), 128>>>(sw_down, ISDIM, y);

    // routed experts
    gemm_gateup<true><<<dim3(IDIM / 64, NTOK / 64, NEXP), 128>>>(x, w_gate, w_up, IDIM);
    gemm_down<true><<<dim3(HDIM / 64, NTOK / 64, NEXP), 128>>>(w_down, IDIM, y);
}

// round 8
// speedup vs baseline: 1.2824x; 1.2824x over previous
#include <cuda_runtime.h>
#include <mma.h>

using namespace nvcuda;

#define HDIM 2048
#define NEXP 16
#define TOPK 4
#define IDIM 1408
#define ISDIM 2816
#define NTOK 1024

// ---------------- scratch (device globals; no allocation) ----------------
__device__ float g_act[(size_t)NEXP * NTOK * IDIM];     // routed SwiGLU activations (UNweighted)
__device__ float g_shact[(size_t)NTOK * ISDIM];         // shared-expert activations
__device__ int   g_list[NEXP * NTOK];                   // token ids per expert (compacted)
__device__ float g_lwt[NEXP * NTOK];                    // combine weight per (expert, slot)
__device__ int   g_cnt[NEXP];                           // tokens per expert
__device__ int   g_tki[NTOK * TOPK];
__device__ float g_tkw[NTOK * TOPK];

// ---------------- cp.async helpers ----------------
__device__ __forceinline__ void cp16(float* dst, const float* src) {
    unsigned d = (unsigned)__cvta_generic_to_shared(dst);
    asm volatile("cp.async.cg.shared.global [%0], [%1], 16;" :: "r"(d), "l"(src));
}
__device__ __forceinline__ void cp_commit() { asm volatile("cp.async.commit_group;"); }
__device__ __forceinline__ void cp_wait0()  { asm volatile("cp.async.wait_group 0;"); }

// ---------------- router: warp per token ----------------
__global__ void router_kernel(const float* __restrict__ x, const float* __restrict__ gw) {
    int warp = threadIdx.x >> 5;
    int lane = threadIdx.x & 31;
    int t = blockIdx.x * 4 + warp;
    if (t >= NTOK) return;

    float acc[NEXP];
#pragma unroll
    for (int e = 0; e < NEXP; e++) acc[e] = 0.f;

    for (int h = lane * 4; h < HDIM; h += 32 * 4) {
        float4 xv = *(const float4*)&x[(size_t)t * HDIM + h];
#pragma unroll
        for (int e = 0; e < NEXP; e++) {
            float4 gv = *(const float4*)&gw[(size_t)e * HDIM + h];
            acc[e] = fmaf(xv.x, gv.x, acc[e]);
            acc[e] = fmaf(xv.y, gv.y, acc[e]);
            acc[e] = fmaf(xv.z, gv.z, acc[e]);
            acc[e] = fmaf(xv.w, gv.w, acc[e]);
        }
    }
#pragma unroll
    for (int e = 0; e < NEXP; e++) {
#pragma unroll
        for (int off = 16; off; off >>= 1)
            acc[e] += __shfl_xor_sync(0xffffffffu, acc[e], off);
    }

    if (lane == 0) {
        float mx = acc[0];
#pragma unroll
        for (int e = 1; e < NEXP; e++) mx = fmaxf(mx, acc[e]);
        float ex[NEXP];
#pragma unroll
        for (int e = 0; e < NEXP; e++) ex[e] = __expf(acc[e] - mx);
        bool used[NEXP];
#pragma unroll
        for (int e = 0; e < NEXP; e++) used[e] = false;
        int idx[TOPK]; float tw[TOPK]; float ws = 0.f;
#pragma unroll
        for (int k = 0; k < TOPK; k++) {
            int bi = -1; float bv = -1.f;
#pragma unroll
            for (int e = 0; e < NEXP; e++)
                if (!used[e] && ex[e] > bv) { bv = ex[e]; bi = e; }
            used[bi] = true; idx[k] = bi; tw[k] = bv; ws += bv;
        }
        float inv = 1.f / ws;
#pragma unroll
        for (int k = 0; k < TOPK; k++) {
            g_tki[t * TOPK + k] = idx[k];
            g_tkw[t * TOPK + k] = tw[k] * inv;
        }
    }
}

// ---------------- deterministic per-expert compaction ----------------
__global__ void build_lists_kernel() {
    int e = blockIdx.x;
    int t = threadIdx.x;   // 1024 threads == NTOK
    bool sel = false; float w = 0.f;
#pragma unroll
    for (int k = 0; k < TOPK; k++) {
        if (g_tki[t * TOPK + k] == e) { sel = true; w = g_tkw[t * TOPK + k]; }
    }
    unsigned m = __ballot_sync(0xffffffffu, sel);
    int lane = t & 31, wid = t >> 5;
    __shared__ int wcnt[32], woff[32];
    if (lane == 0) wcnt[wid] = __popc(m);
    __syncthreads();
    if (t < 32) {
        int v = wcnt[t];
        int s = v;
#pragma unroll
        for (int off = 1; off < 32; off <<= 1) {
            int o = __shfl_up_sync(0xffffffffu, s, off);
            if (t >= off) s += o;
        }
        woff[t] = s - v;
        if (t == 31) g_cnt[e] = s;
    }
    __syncthreads();
    if (sel) {
        int pos = woff[wid] + __popc(m & ((1u << lane) - 1));
        g_list[e * NTOK + pos] = t;
        g_lwt[e * NTOK + pos] = w;
    }
}

// =====================================================================
// GEMM1: fused gate+up + SwiGLU (no combine weight; applied in down).
// BM=128, BN=64, BK=16, 256 threads, 8 warps (4x2), warp tile 32x32.
// cp.async 2-stage double buffer. smem strides: A 24, B 68 (padded).
// =====================================================================
#define GU_ASTR 24
#define GU_BSTR 68
#define GU_ABUF (128 * GU_ASTR)     // 3072 floats per stage
#define GU_BBUF (16 * GU_BSTR)      // 1088 floats per stage
// dynamic smem floats: 2*GU_ABUF + 4*GU_BBUF = 6144 + 4352 = 10496 (41984 B)
#define GU_SMEM_BYTES (10496 * 4)

template <bool ROUTED>
__global__ __launch_bounds__(256)
void gemm_gateup(const float* __restrict__ X,
                 const float* __restrict__ Wg,
                 const float* __restrict__ Wu,
                 int ldb) {
    extern __shared__ float smem[];
    float* As = smem;                      // [2][128*24]
    float* Bg = smem + 2 * GU_ABUF;        // [2][16*68]
    float* Bu = Bg + 2 * GU_BBUF;          // [2][16*68]

    __shared__ int rowtok[128];

    const int tid = threadIdx.x;
    const int wid = tid >> 5;
    const int wm = wid & 3;        // 0..3
    const int wn = wid >> 2;       // 0..1

    const int n0 = blockIdx.x * 64;
    const int m0 = blockIdx.y * 128;

    int e = 0, cnt = NTOK;
    const float* bg = Wg;
    const float* bu = Wu;
    if (ROUTED) {
        e = blockIdx.z;
        cnt = g_cnt[e];
        if (m0 >= cnt) return;
        bg = Wg + (size_t)e * HDIM * IDIM;
        bu = Wu + (size_t)e * HDIM * IDIM;
    }

    if (tid < 128) {
        int slot = m0 + tid;
        if (ROUTED) rowtok[tid] = (slot < cnt) ? g_list[e * NTOK + slot] : g_list[e * NTOK];
        else        rowtok[tid] = slot;
    }
    __syncthreads();

    // tile loader: A 512 float4 (2/thread), Bg/Bu 256 float4 each (1/thread)
    auto load_tile = [&](int kt, int buf) {
        int k0 = kt * 16;
        float* as  = As + buf * GU_ABUF;
        float* bgs = Bg + buf * GU_BBUF;
        float* bus = Bu + buf * GU_BBUF;
        int f4 = tid;
#pragma unroll
        for (int q = 0; q < 2; q++, f4 += 256) {
            int r = f4 >> 2, c4 = (f4 & 3) * 4;
            cp16(&as[r * GU_ASTR + c4], &X[(size_t)rowtok[r] * HDIM + k0 + c4]);
        }
        int r = tid >> 4, c4 = (tid & 15) * 4;
        size_t g = (size_t)(k0 + r) * ldb + n0 + c4;
        cp16(&bgs[r * GU_BSTR + c4], &bg[g]);
        cp16(&bus[r * GU_BSTR + c4], &bu[g]);
        cp_commit();
    };

    wmma::fragment<wmma::accumulator, 16, 16, 8, float> accg[2][2], accu[2][2];
#pragma unroll
    for (int i = 0; i < 2; i++)
#pragma unroll
        for (int j = 0; j < 2; j++) {
            wmma::fill_fragment(accg[i][j], 0.f);
            wmma::fill_fragment(accu[i][j], 0.f);
        }

    const int KT = HDIM / 16;   // 128
    load_tile(0, 0);
    for (int kt = 0; kt < KT; kt++) {
        cp_wait0();
        __syncthreads();
        if (kt + 1 < KT) load_tile(kt + 1, (kt + 1) & 1);

        int buf = kt & 1;
        float* as  = As + buf * GU_ABUF;
        float* bgs = Bg + buf * GU_BBUF;
        float* bus = Bu + buf * GU_BBUF;
#pragma unroll
        for (int kk = 0; kk < 16; kk += 8) {
            wmma::fragment<wmma::matrix_a, 16, 16, 8, wmma::precision::tf32, wmma::row_major> fa[2];
            wmma::fragment<wmma::matrix_b, 16, 16, 8, wmma::precision::tf32, wmma::row_major> fbg[2], fbu[2];
#pragma unroll
            for (int i = 0; i < 2; i++) {
                wmma::load_matrix_sync(fa[i], &as[(wm * 32 + i * 16) * GU_ASTR + kk], GU_ASTR);
#pragma unroll
                for (int t = 0; t < fa[i].num_elements; t++)
                    fa[i].x[t] = wmma::__float_to_tf32(fa[i].x[t]);
            }
#pragma unroll
            for (int j = 0; j < 2; j++) {
                wmma::load_matrix_sync(fbg[j], &bgs[kk * GU_BSTR + wn * 32 + j * 16], GU_BSTR);
                wmma::load_matrix_sync(fbu[j], &bus[kk * GU_BSTR + wn * 32 + j * 16], GU_BSTR);
#pragma unroll
                for (int t = 0; t < fbg[j].num_elements; t++) {
                    fbg[j].x[t] = wmma::__float_to_tf32(fbg[j].x[t]);
                    fbu[j].x[t] = wmma::__float_to_tf32(fbu[j].x[t]);
                }
            }
#pragma unroll
            for (int i = 0; i < 2; i++)
#pragma unroll
                for (int j = 0; j < 2; j++) {
                    wmma::mma_sync(accg[i][j], fa[i], fbg[j], accg[i][j]);
                    wmma::mma_sync(accu[i][j], fa[i], fbu[j], accu[i][j]);
                }
        }
    }
    __syncthreads();   // pipeline buffers dead; alias Cs over them

    // SwiGLU elementwise on fragments (accg/accu share element->coord map)
    float* Cs = smem;  // [128][68]
#pragma unroll
    for (int i = 0; i < 2; i++)
#pragma unroll
        for (int j = 0; j < 2; j++) {
#pragma unroll
            for (int t = 0; t < accg[i][j].num_elements; t++) {
                float gv = accg[i][j].x[t];
                accg[i][j].x[t] = gv / (1.f + __expf(-gv)) * accu[i][j].x[t];
            }
            wmma::store_matrix_sync(&Cs[(wm * 32 + i * 16) * GU_BSTR + wn * 32 + j * 16],
                                    accg[i][j], GU_BSTR, wmma::mem_row_major);
        }
    __syncthreads();

    for (int t4 = tid; t4 < 128 * 16; t4 += 256) {
        int r = t4 >> 4, c4 = (t4 & 15) * 4;
        float4 v = *(float4*)&Cs[r * GU_BSTR + c4];
        if (ROUTED)
            *(float4*)&g_act[((size_t)(e * NTOK + m0 + r)) * IDIM + n0 + c4] = v;
        else
            *(float4*)&g_shact[(size_t)(m0 + r) * ISDIM + n0 + c4] = v;
    }
}

// =====================================================================
// GEMM2: down projection. BM=128, BN=128, BK=16, 256 threads,
// 8 warps (4x2), warp tile 32x64 (2x4 frags). Combine weight applied here.
// =====================================================================
#define DN_ASTR 24
#define DN_BSTR 132
#define DN_ABUF (128 * DN_ASTR)     // 3072
#define DN_BBUF (16 * DN_BSTR)      // 2112
#define DN_CSTR 132
// tiles: 2*3072 + 2*2112 = 10368 floats (41472 B); Cs alias needs 128*132 = 16896 floats (67584 B)
#define DN_SMEM_BYTES (16896 * 4)

template <bool ROUTED>
__global__ __launch_bounds__(256)
void gemm_down(const float* __restrict__ W, int KK, float* __restrict__ Y) {
    extern __shared__ float smem[];
    float* As = smem;                     // [2][128*24]
    float* Bs = smem + 2 * DN_ABUF;       // [2][16*132]

    __shared__ int   rowtok[128];
    __shared__ float roww[128];

    const int tid = threadIdx.x;
    const int wid = tid >> 5;
    const int wm = wid & 3;
    const int wn = wid >> 2;

    const int n0 = blockIdx.x * 128;
    const int m0 = blockIdx.y * 128;

    int e = 0, cnt = NTOK;
    const float* bw = W;
    const float* Abase;
    int lda;
    if (ROUTED) {
        e = blockIdx.z;
        cnt = g_cnt[e];
        if (m0 >= cnt) return;
        bw = W + (size_t)e * IDIM * HDIM;
        Abase = g_act + (size_t)e * NTOK * IDIM;
        lda = IDIM;
    } else {
        Abase = g_shact;
        lda = ISDIM;
    }

    if (tid < 128) {
        int slot = m0 + tid;
        if (ROUTED) {
            rowtok[tid] = (slot < cnt) ? g_list[e * NTOK + slot] : -1;
            roww[tid]   = (slot < cnt) ? g_lwt[e * NTOK + slot] : 0.f;
        }
    }

    auto load_tile = [&](int kt, int buf) {
        int k0 = kt * 16;
        float* as = As + buf * DN_ABUF;
        float* bs = Bs + buf * DN_BBUF;
        int f4 = tid;
#pragma unroll
        for (int q = 0; q < 2; q++, f4 += 256) {
            int r = f4 >> 2, c4 = (f4 & 3) * 4;
            cp16(&as[r * DN_ASTR + c4], &Abase[(size_t)(m0 + r) * lda + k0 + c4]);
        }
        f4 = tid;
#pragma unroll
        for (int q = 0; q < 2; q++, f4 += 256) {
            int r = f4 >> 5, c4 = (f4 & 31) * 4;
            cp16(&bs[r * DN_BSTR + c4], &bw[(size_t)(k0 + r) * HDIM + n0 + c4]);
        }
        cp_commit();
    };

    wmma::fragment<wmma::accumulator, 16, 16, 8, float> acc[2][4];
#pragma unroll
    for (int i = 0; i < 2; i++)
#pragma unroll
        for (int j = 0; j < 4; j++) wmma::fill_fragment(acc[i][j], 0.f);

    const int KT = KK / 16;
    load_tile(0, 0);
    for (int kt = 0; kt < KT; kt++) {
        cp_wait0();
        __syncthreads();
        if (kt + 1 < KT) load_tile(kt + 1, (kt + 1) & 1);

        int buf = kt & 1;
        float* as = As + buf * DN_ABUF;
        float* bs = Bs + buf * DN_BBUF;
#pragma unroll
        for (int kk = 0; kk < 16; kk += 8) {
            wmma::fragment<wmma::matrix_a, 16, 16, 8, wmma::precision::tf32, wmma::row_major> fa[2];
            wmma::fragment<wmma::matrix_b, 16, 16, 8, wmma::precision::tf32, wmma::row_major> fb[4];
#pragma unroll
            for (int i = 0; i < 2; i++) {
                wmma::load_matrix_sync(fa[i], &as[(wm * 32 + i * 16) * DN_ASTR + kk], DN_ASTR);
#pragma unroll
                for (int t = 0; t < fa[i].num_elements; t++)
                    fa[i].x[t] = wmma::__float_to_tf32(fa[i].x[t]);
            }
#pragma unroll
            for (int j = 0; j < 4; j++) {
                wmma::load_matrix_sync(fb[j], &bs[kk * DN_BSTR + wn * 64 + j * 16], DN_BSTR);
#pragma unroll
                for (int t = 0; t < fb[j].num_elements; t++)
                    fb[j].x[t] = wmma::__float_to_tf32(fb[j].x[t]);
            }
#pragma unroll
            for (int i = 0; i < 2; i++)
#pragma unroll
                for (int j = 0; j < 4; j++)
                    wmma::mma_sync(acc[i][j], fa[i], fb[j], acc[i][j]);
        }
    }
    __syncthreads();   // pipeline buffers dead; alias Cs

    float* Cs = smem;  // [128][132]
#pragma unroll
    for (int i = 0; i < 2; i++)
#pragma unroll
        for (int j = 0; j < 4; j++)
            wmma::store_matrix_sync(&Cs[(wm * 32 + i * 16) * DN_CSTR + wn * 64 + j * 16],
                                    acc[i][j], DN_CSTR, wmma::mem_row_major);
    __syncthreads();

    for (int t4 = tid; t4 < 128 * 32; t4 += 256) {
        int r = t4 >> 5, c4 = (t4 & 31) * 4;
        float4 v = *(float4*)&Cs[r * DN_CSTR + c4];
        if (ROUTED) {
            int t = rowtok[r];
            if (t >= 0) {
                float w = roww[r];
                float* yp = &Y[(size_t)t * HDIM + n0 + c4];
                atomicAdd(yp + 0, v.x * w);
                atomicAdd(yp + 1, v.y * w);
                atomicAdd(yp + 2, v.z * w);
                atomicAdd(yp + 3, v.w * w);
            }
        } else {
            *(float4*)&Y[(size_t)(m0 + r) * HDIM + n0 + c4] = v;
        }
    }
}

// ---------------- launch ----------------
extern "C" void kernel_launch(void* const* d_in, const int* in_sizes, int n_in,
                              void* d_out, int out_size) {
    const float* x       = (const float*)d_in[0];
    const float* gate_w  = (const float*)d_in[1];
    const float* w_gate  = (const float*)d_in[2];
    const float* w_up    = (const float*)d_in[3];
    const float* w_down  = (const float*)d_in[4];
    const float* sw_gate = (const float*)d_in[5];
    const float* sw_up   = (const float*)d_in[6];
    const float* sw_down = (const float*)d_in[7];
    float* y = (float*)d_out;

    // unconditional, idempotent, host-side (not a stream op; capture-safe;
    // no static state so kernel_launch is fully deterministic per the rules)
    cudaFuncSetAttribute((const void*)gemm_down<false>,
                         cudaFuncAttributeMaxDynamicSharedMemorySize, DN_SMEM_BYTES);
    cudaFuncSetAttribute((const void*)gemm_down<true>,
                         cudaFuncAttributeMaxDynamicSharedMemorySize, DN_SMEM_BYTES);

    router_kernel<<<NTOK / 4, 128>>>(x, gate_w);
    build_lists_kernel<<<NEXP, NTOK>>>();

    // shared expert first (down<false> writes y fully, before routed scatter-adds)
    gemm_gateup<false><<<dim3(ISDIM / 64, NTOK / 128), 256, GU_SMEM_BYTES>>>(x, sw_gate, sw_up, ISDIM);
    gemm_down<false><<<dim3(HDIM / 128, NTOK / 128), 256, DN_SMEM_BYTES>>>(sw_down, ISDIM, y);

    // routed experts
    gemm_gateup<true><<<dim3(IDIM / 64, NTOK / 128, NEXP), 256, GU_SMEM_BYTES>>>(x, w_gate, w_up, IDIM);
    gemm_down<true><<<dim3(HDIM / 128, NTOK / 128, NEXP), 256, DN_SMEM_BYTES>>>(w_down, IDIM, y);
}

// round 9
// speedup vs baseline: 1.2840x; 1.0013x over previous
#include <cuda_runtime.h>
#include <mma.h>

using namespace nvcuda;

#define HDIM 2048
#define NEXP 16
#define TOPK 4
#define IDIM 1408
#define ISDIM 2816
#define NTOK 1024

// ---------------- scratch (device globals; no allocation) ----------------
__device__ float g_act[(size_t)NEXP * NTOK * IDIM];     // routed SwiGLU activations (UNweighted)
__device__ float g_shact[(size_t)NTOK * ISDIM];         // shared-expert activations
__device__ int   g_list[NEXP * NTOK];                   // token ids per expert (compacted)
__device__ float g_lwt[NEXP * NTOK];                    // combine weight per (expert, slot)
__device__ int   g_cnt[NEXP];                           // tokens per expert
__device__ int   g_tki[NTOK * TOPK];
__device__ float g_tkw[NTOK * TOPK];

// ---------------- cp.async helpers ----------------
__device__ __forceinline__ void cp16(float* dst, const float* src) {
    unsigned d = (unsigned)__cvta_generic_to_shared(dst);
    asm volatile("cp.async.cg.shared.global [%0], [%1], 16;" :: "r"(d), "l"(src));
}
__device__ __forceinline__ void cp_commit() { asm volatile("cp.async.commit_group;"); }
__device__ __forceinline__ void cp_wait0()  { asm volatile("cp.async.wait_group 0;"); }
__device__ __forceinline__ void cp_wait1()  { asm volatile("cp.async.wait_group 1;"); }

// ---------------- router: warp per token ----------------
__global__ void router_kernel(const float* __restrict__ x, const float* __restrict__ gw) {
    int warp = threadIdx.x >> 5;
    int lane = threadIdx.x & 31;
    int t = blockIdx.x * 4 + warp;
    if (t >= NTOK) return;

    float acc[NEXP];
#pragma unroll
    for (int e = 0; e < NEXP; e++) acc[e] = 0.f;

    for (int h = lane * 4; h < HDIM; h += 32 * 4) {
        float4 xv = *(const float4*)&x[(size_t)t * HDIM + h];
#pragma unroll
        for (int e = 0; e < NEXP; e++) {
            float4 gv = *(const float4*)&gw[(size_t)e * HDIM + h];
            acc[e] = fmaf(xv.x, gv.x, acc[e]);
            acc[e] = fmaf(xv.y, gv.y, acc[e]);
            acc[e] = fmaf(xv.z, gv.z, acc[e]);
            acc[e] = fmaf(xv.w, gv.w, acc[e]);
        }
    }
#pragma unroll
    for (int e = 0; e < NEXP; e++) {
#pragma unroll
        for (int off = 16; off; off >>= 1)
            acc[e] += __shfl_xor_sync(0xffffffffu, acc[e], off);
    }

    if (lane == 0) {
        float mx = acc[0];
#pragma unroll
        for (int e = 1; e < NEXP; e++) mx = fmaxf(mx, acc[e]);
        float ex[NEXP];
#pragma unroll
        for (int e = 0; e < NEXP; e++) ex[e] = __expf(acc[e] - mx);
        bool used[NEXP];
#pragma unroll
        for (int e = 0; e < NEXP; e++) used[e] = false;
        int idx[TOPK]; float tw[TOPK]; float ws = 0.f;
#pragma unroll
        for (int k = 0; k < TOPK; k++) {
            int bi = -1; float bv = -1.f;
#pragma unroll
            for (int e = 0; e < NEXP; e++)
                if (!used[e] && ex[e] > bv) { bv = ex[e]; bi = e; }
            used[bi] = true; idx[k] = bi; tw[k] = bv; ws += bv;
        }
        float inv = 1.f / ws;
#pragma unroll
        for (int k = 0; k < TOPK; k++) {
            g_tki[t * TOPK + k] = idx[k];
            g_tkw[t * TOPK + k] = tw[k] * inv;
        }
    }
}

// ---------------- deterministic per-expert compaction ----------------
__global__ void build_lists_kernel() {
    int e = blockIdx.x;
    int t = threadIdx.x;   // 1024 threads == NTOK
    bool sel = false; float w = 0.f;
#pragma unroll
    for (int k = 0; k < TOPK; k++) {
        if (g_tki[t * TOPK + k] == e) { sel = true; w = g_tkw[t * TOPK + k]; }
    }
    unsigned m = __ballot_sync(0xffffffffu, sel);
    int lane = t & 31, wid = t >> 5;
    __shared__ int wcnt[32], woff[32];
    if (lane == 0) wcnt[wid] = __popc(m);
    __syncthreads();
    if (t < 32) {
        int v = wcnt[t];
        int s = v;
#pragma unroll
        for (int off = 1; off < 32; off <<= 1) {
            int o = __shfl_up_sync(0xffffffffu, s, off);
            if (t >= off) s += o;
        }
        woff[t] = s - v;
        if (t == 31) g_cnt[e] = s;
    }
    __syncthreads();
    if (sel) {
        int pos = woff[wid] + __popc(m & ((1u << lane) - 1));
        g_list[e * NTOK + pos] = t;
        g_lwt[e * NTOK + pos] = w;
    }
}

// =====================================================================
// GEMM1: fused gate+up + SwiGLU (combine weight applied in down).
// BM=128, BN=64, BK=16, 256 threads, 8 warps (4x2), warp tile 32x32.
// 3-stage cp.async pipeline; epilogue stores fragments DIRECT to global.
// =====================================================================
#define GU_ASTR 24
#define GU_BSTR 68
#define GU_ABUF (128 * GU_ASTR)     // 3072 floats per stage
#define GU_BBUF (16 * GU_BSTR)      // 1088 floats per stage
#define GU_SMEM_BYTES ((3 * GU_ABUF + 6 * GU_BBUF) * 4)   // 62976 B

template <bool ROUTED>
__global__ __launch_bounds__(256, 2)
void gemm_gateup(const float* __restrict__ X,
                 const float* __restrict__ Wg,
                 const float* __restrict__ Wu,
                 int ldb) {
    extern __shared__ float smem[];
    float* As = smem;                      // [3][128*24]
    float* Bg = smem + 3 * GU_ABUF;        // [3][16*68]
    float* Bu = Bg + 3 * GU_BBUF;          // [3][16*68]

    __shared__ int rowtok[128];

    const int tid = threadIdx.x;
    const int wid = tid >> 5;
    const int wm = wid & 3;        // 0..3
    const int wn = wid >> 2;       // 0..1

    const int n0 = blockIdx.x * 64;
    const int m0 = blockIdx.y * 128;

    int e = 0, cnt = NTOK;
    const float* bg = Wg;
    const float* bu = Wu;
    if (ROUTED) {
        e = blockIdx.z;
        cnt = g_cnt[e];
        if (m0 >= cnt) return;
        bg = Wg + (size_t)e * HDIM * IDIM;
        bu = Wu + (size_t)e * HDIM * IDIM;
    }

    if (tid < 128) {
        int slot = m0 + tid;
        if (ROUTED) rowtok[tid] = (slot < cnt) ? g_list[e * NTOK + slot] : g_list[e * NTOK];
        else        rowtok[tid] = slot;
    }
    __syncthreads();

    auto load_tile = [&](int kt, int buf) {
        int k0 = kt * 16;
        float* as  = As + buf * GU_ABUF;
        float* bgs = Bg + buf * GU_BBUF;
        float* bus = Bu + buf * GU_BBUF;
        int f4 = tid;
#pragma unroll
        for (int q = 0; q < 2; q++, f4 += 256) {
            int r = f4 >> 2, c4 = (f4 & 3) * 4;
            cp16(&as[r * GU_ASTR + c4], &X[(size_t)rowtok[r] * HDIM + k0 + c4]);
        }
        int r = tid >> 4, c4 = (tid & 15) * 4;
        size_t g = (size_t)(k0 + r) * ldb + n0 + c4;
        cp16(&bgs[r * GU_BSTR + c4], &bg[g]);
        cp16(&bus[r * GU_BSTR + c4], &bu[g]);
        cp_commit();
    };

    wmma::fragment<wmma::accumulator, 16, 16, 8, float> accg[2][2], accu[2][2];
#pragma unroll
    for (int i = 0; i < 2; i++)
#pragma unroll
        for (int j = 0; j < 2; j++) {
            wmma::fill_fragment(accg[i][j], 0.f);
            wmma::fill_fragment(accu[i][j], 0.f);
        }

    const int KT = HDIM / 16;   // 128
    load_tile(0, 0);
    load_tile(1, 1);
    int buf = 0;
    for (int kt = 0; kt < KT; kt++) {
        if (kt + 1 < KT) cp_wait1(); else cp_wait0();
        __syncthreads();
        if (kt + 2 < KT) {
            int nb = buf + 2; if (nb >= 3) nb -= 3;
            load_tile(kt + 2, nb);
        }

        float* as  = As + buf * GU_ABUF;
        float* bgs = Bg + buf * GU_BBUF;
        float* bus = Bu + buf * GU_BBUF;
#pragma unroll
        for (int kk = 0; kk < 16; kk += 8) {
            wmma::fragment<wmma::matrix_a, 16, 16, 8, wmma::precision::tf32, wmma::row_major> fa[2];
            wmma::fragment<wmma::matrix_b, 16, 16, 8, wmma::precision::tf32, wmma::row_major> fbg[2], fbu[2];
#pragma unroll
            for (int i = 0; i < 2; i++) {
                wmma::load_matrix_sync(fa[i], &as[(wm * 32 + i * 16) * GU_ASTR + kk], GU_ASTR);
#pragma unroll
                for (int t = 0; t < fa[i].num_elements; t++)
                    fa[i].x[t] = wmma::__float_to_tf32(fa[i].x[t]);
            }
#pragma unroll
            for (int j = 0; j < 2; j++) {
                wmma::load_matrix_sync(fbg[j], &bgs[kk * GU_BSTR + wn * 32 + j * 16], GU_BSTR);
                wmma::load_matrix_sync(fbu[j], &bus[kk * GU_BSTR + wn * 32 + j * 16], GU_BSTR);
#pragma unroll
                for (int t = 0; t < fbg[j].num_elements; t++) {
                    fbg[j].x[t] = wmma::__float_to_tf32(fbg[j].x[t]);
                    fbu[j].x[t] = wmma::__float_to_tf32(fbu[j].x[t]);
                }
            }
#pragma unroll
            for (int i = 0; i < 2; i++)
#pragma unroll
                for (int j = 0; j < 2; j++) {
                    wmma::mma_sync(accg[i][j], fa[i], fbg[j], accg[i][j]);
                    wmma::mma_sync(accu[i][j], fa[i], fbu[j], accu[i][j]);
                }
        }
        if (++buf >= 3) buf = 0;
    }

    // SwiGLU elementwise on fragments, then store DIRECT to global.
    // (accg/accu share element->coord map; rows are contiguous in scratch)
#pragma unroll
    for (int i = 0; i < 2; i++)
#pragma unroll
        for (int j = 0; j < 2; j++) {
#pragma unroll
            for (int t = 0; t < accg[i][j].num_elements; t++) {
                float gv = accg[i][j].x[t];
                accg[i][j].x[t] = gv / (1.f + __expf(-gv)) * accu[i][j].x[t];
            }
            int rbase = m0 + wm * 32 + i * 16;
            int cbase = n0 + wn * 32 + j * 16;
            if (ROUTED)
                wmma::store_matrix_sync(&g_act[((size_t)(e * NTOK) + rbase) * IDIM + cbase],
                                        accg[i][j], IDIM, wmma::mem_row_major);
            else
                wmma::store_matrix_sync(&g_shact[(size_t)rbase * ISDIM + cbase],
                                        accg[i][j], ISDIM, wmma::mem_row_major);
        }
}

// =====================================================================
// GEMM2: down projection. BM=128, BN=128, BK=16, 256 threads,
// 8 warps (4x2), warp tile 32x64 (2x4 frags). Combine weight applied here.
// 3-stage pipeline. Shared path: direct fragment stores to Y.
// Routed path: half-staged smem epilogue + weighted atomicAdd scatter.
// =====================================================================
#define DN_ASTR 24
#define DN_BSTR 132
#define DN_ABUF (128 * DN_ASTR)     // 3072
#define DN_BBUF (16 * DN_BSTR)      // 2112
#define DN_CSTR 132
#define DN_SMEM_BYTES ((3 * (DN_ABUF + DN_BBUF)) * 4)   // 62208 B  (Cs half = 64*132 = 33792 B aliases within)

template <bool ROUTED>
__global__ __launch_bounds__(256, 2)
void gemm_down(const float* __restrict__ W, int KK, float* __restrict__ Y) {
    extern __shared__ float smem[];
    float* As = smem;                     // [3][128*24]
    float* Bs = smem + 3 * DN_ABUF;       // [3][16*132]

    __shared__ int   rowtok[128];
    __shared__ float roww[128];

    const int tid = threadIdx.x;
    const int wid = tid >> 5;
    const int wm = wid & 3;
    const int wn = wid >> 2;

    const int n0 = blockIdx.x * 128;
    const int m0 = blockIdx.y * 128;

    int e = 0, cnt = NTOK;
    const float* bw = W;
    const float* Abase;
    int lda;
    if (ROUTED) {
        e = blockIdx.z;
        cnt = g_cnt[e];
        if (m0 >= cnt) return;
        bw = W + (size_t)e * IDIM * HDIM;
        Abase = g_act + (size_t)e * NTOK * IDIM;
        lda = IDIM;
    } else {
        Abase = g_shact;
        lda = ISDIM;
    }

    if (ROUTED && tid < 128) {
        int slot = m0 + tid;
        rowtok[tid] = (slot < cnt) ? g_list[e * NTOK + slot] : -1;
        roww[tid]   = (slot < cnt) ? g_lwt[e * NTOK + slot] : 0.f;
    }

    auto load_tile = [&](int kt, int buf) {
        int k0 = kt * 16;
        float* as = As + buf * DN_ABUF;
        float* bs = Bs + buf * DN_BBUF;
        int f4 = tid;
#pragma unroll
        for (int q = 0; q < 2; q++, f4 += 256) {
            int r = f4 >> 2, c4 = (f4 & 3) * 4;
            cp16(&as[r * DN_ASTR + c4], &Abase[(size_t)(m0 + r) * lda + k0 + c4]);
        }
        f4 = tid;
#pragma unroll
        for (int q = 0; q < 2; q++, f4 += 256) {
            int r = f4 >> 5, c4 = (f4 & 31) * 4;
            cp16(&bs[r * DN_BSTR + c4], &bw[(size_t)(k0 + r) * HDIM + n0 + c4]);
        }
        cp_commit();
    };

    wmma::fragment<wmma::accumulator, 16, 16, 8, float> acc[2][4];
#pragma unroll
    for (int i = 0; i < 2; i++)
#pragma unroll
        for (int j = 0; j < 4; j++) wmma::fill_fragment(acc[i][j], 0.f);

    const int KT = KK / 16;
    load_tile(0, 0);
    load_tile(1, 1);
    int buf = 0;
    for (int kt = 0; kt < KT; kt++) {
        if (kt + 1 < KT) cp_wait1(); else cp_wait0();
        __syncthreads();
        if (kt + 2 < KT) {
            int nb = buf + 2; if (nb >= 3) nb -= 3;
            load_tile(kt + 2, nb);
        }

        float* as = As + buf * DN_ABUF;
        float* bs = Bs + buf * DN_BBUF;
#pragma unroll
        for (int kk = 0; kk < 16; kk += 8) {
            wmma::fragment<wmma::matrix_a, 16, 16, 8, wmma::precision::tf32, wmma::row_major> fa[2];
            wmma::fragment<wmma::matrix_b, 16, 16, 8, wmma::precision::tf32, wmma::row_major> fb[4];
#pragma unroll
            for (int i = 0; i < 2; i++) {
                wmma::load_matrix_sync(fa[i], &as[(wm * 32 + i * 16) * DN_ASTR + kk], DN_ASTR);
#pragma unroll
                for (int t = 0; t < fa[i].num_elements; t++)
                    fa[i].x[t] = wmma::__float_to_tf32(fa[i].x[t]);
            }
#pragma unroll
            for (int j = 0; j < 4; j++) {
                wmma::load_matrix_sync(fb[j], &bs[kk * DN_BSTR + wn * 64 + j * 16], DN_BSTR);
#pragma unroll
                for (int t = 0; t < fb[j].num_elements; t++)
                    fb[j].x[t] = wmma::__float_to_tf32(fb[j].x[t]);
            }
#pragma unroll
            for (int i = 0; i < 2; i++)
#pragma unroll
                for (int j = 0; j < 4; j++)
                    wmma::mma_sync(acc[i][j], fa[i], fb[j], acc[i][j]);
        }
        if (++buf >= 3) buf = 0;
    }

    if (!ROUTED) {
        // direct fragment stores: Y rows are m0+..., contiguous
#pragma unroll
        for (int i = 0; i < 2; i++)
#pragma unroll
            for (int j = 0; j < 4; j++)
                wmma::store_matrix_sync(&Y[(size_t)(m0 + wm * 32 + i * 16) * HDIM + n0 + wn * 64 + j * 16],
                                        acc[i][j], HDIM, wmma::mem_row_major);
    } else {
        // half-staged smem epilogue: 64 rows at a time (rows wm*32+i*16..+15 -> Cs row wm*16..)
        float* Cs = smem;   // 64 x 132 floats, aliases dead pipeline buffers
#pragma unroll
        for (int i = 0; i < 2; i++) {
            __syncthreads();
#pragma unroll
            for (int j = 0; j < 4; j++)
                wmma::store_matrix_sync(&Cs[(wm * 16) * DN_CSTR + wn * 64 + j * 16],
                                        acc[i][j], DN_CSTR, wmma::mem_row_major);
            __syncthreads();
            for (int t4 = tid; t4 < 64 * 32; t4 += 256) {
                int rr = t4 >> 5, c4 = (t4 & 31) * 4;
                int lr = (rr >> 4) * 32 + i * 16 + (rr & 15);   // local row in [0,128)
                int t = rowtok[lr];
                if (t >= 0) {
                    float w = roww[lr];
                    float4 v = *(float4*)&Cs[rr * DN_CSTR + c4];
                    float* yp = &Y[(size_t)t * HDIM + n0 + c4];
                    atomicAdd(yp + 0, v.x * w);
                    atomicAdd(yp + 1, v.y * w);
                    atomicAdd(yp + 2, v.z * w);
                    atomicAdd(yp + 3, v.w * w);
                }
            }
        }
    }
}

// ---------------- launch ----------------
extern "C" void kernel_launch(void* const* d_in, const int* in_sizes, int n_in,
                              void* d_out, int out_size) {
    const float* x       = (const float*)d_in[0];
    const float* gate_w  = (const float*)d_in[1];
    const float* w_gate  = (const float*)d_in[2];
    const float* w_up    = (const float*)d_in[3];
    const float* w_down  = (const float*)d_in[4];
    const float* sw_gate = (const float*)d_in[5];
    const float* sw_up   = (const float*)d_in[6];
    const float* sw_down = (const float*)d_in[7];
    float* y = (float*)d_out;

    // unconditional, idempotent, host-side, capture-safe
    cudaFuncSetAttribute((const void*)gemm_gateup<false>,
                         cudaFuncAttributeMaxDynamicSharedMemorySize, GU_SMEM_BYTES);
    cudaFuncSetAttribute((const void*)gemm_gateup<true>,
                         cudaFuncAttributeMaxDynamicSharedMemorySize, GU_SMEM_BYTES);
    cudaFuncSetAttribute((const void*)gemm_down<false>,
                         cudaFuncAttributeMaxDynamicSharedMemorySize, DN_SMEM_BYTES);
    cudaFuncSetAttribute((const void*)gemm_down<true>,
                         cudaFuncAttributeMaxDynamicSharedMemorySize, DN_SMEM_BYTES);

    router_kernel<<<NTOK / 4, 128>>>(x, gate_w);
    build_lists_kernel<<<NEXP, NTOK>>>();

    // shared expert first (down<false> writes y fully, before routed scatter-adds)
    gemm_gateup<false><<<dim3(ISDIM / 64, NTOK / 128), 256, GU_SMEM_BYTES>>>(x, sw_gate, sw_up, ISDIM);
    gemm_down<false><<<dim3(HDIM / 128, NTOK / 128), 256, DN_SMEM_BYTES>>>(sw_down, ISDIM, y);

    // routed experts
    gemm_gateup<true><<<dim3(IDIM / 64, NTOK / 128, NEXP), 256, GU_SMEM_BYTES>>>(x, w_gate, w_up, IDIM);
    gemm_down<true><<<dim3(HDIM / 128, NTOK / 128, NEXP), 256, DN_SMEM_BYTES>>>(w_down, IDIM, y);
}